// round 4
// baseline (speedup 1.0000x reference)
#include <cuda_runtime.h>
#include <stdint.h>

#define N_MAXN 150000
#define E_MAXE 2400000
#define F_IN 22
#define F_PAD 24
#define HID 32
#define N_CLS 6
#define BN_EPS 1e-5f
#define MAXDEG 64

// ---------------- device scratch (no allocations allowed) ----------------
__device__ __align__(16) float g_hs[N_MAXN * HID];     // dis[node] * ((relu(xWe+be))Wg)
__device__ __align__(16) float g_agg[N_MAXN * HID];    // aggregated messages
__device__ int   g_cnt[N_MAXN];                        // in-degree (excl. self loop)
__device__ int   g_pad[(size_t)N_MAXN * MAXDEG];       // padded CSR: src lists per dst
__device__ float g_sum[HID];
__device__ float g_sumsq[HID];
__device__ float g_scale[HID];
__device__ float g_shift[HID];
__device__ int   g_is64;

// ---------------- dtype detection for edge_index (1 warp) ----------------
__global__ void k_detect(const long long* __restrict__ ei, int n) {
    int t = threadIdx.x;
    long long v0 = ei[t];
    long long v1 = ei[t + 32];
    int bad = (v0 < 0) | (v0 >= (long long)n) | (v1 < 0) | (v1 >= (long long)n);
    unsigned m = __ballot_sync(0xffffffffu, bad);
    if (t == 0) g_is64 = (m == 0u);
}

// ---------------- zero counters + BN accumulators ----------------
__global__ void k_zero(int n) {
    int i = blockIdx.x * blockDim.x + threadIdx.x;
    if (i < n) g_cnt[i] = 0;
    if (i < HID) { g_sum[i] = 0.0f; g_sumsq[i] = 0.0f; }
}

// ---------------- build padded CSR: pad[d][pos] = s ----------------
__global__ void k_build(const void* __restrict__ ei, int e) {
    int i = blockIdx.x * blockDim.x + threadIdx.x;
    if (i >= e) return;
    int s, d;
    if (g_is64) {
        const long long* p = (const long long*)ei;
        s = (int)p[i];
        d = (int)p[(size_t)e + i];
    } else {
        const int* p = (const int*)ei;
        s = p[i];
        d = p[(size_t)e + i];
    }
    int pos = atomicAdd(&g_cnt[d], 1);
    if (pos < MAXDEG) g_pad[(size_t)d * MAXDEG + pos] = s;
}

// ---------------- fused MLP: hs = dis * (relu(x@W_emb + b_emb) @ W_gcn) ----------------
// Weights in shared with vectorized (float4) access: W_emb transposed to
// [HID][F_PAD] so each output j reads a contiguous 24-float row.
__global__ void __launch_bounds__(128)
k_mlp(const float* __restrict__ x, const float* __restrict__ Wemb,
      const float* __restrict__ bemb, const float* __restrict__ Wgcn, int n) {
    __shared__ __align__(16) float sWeT[HID * F_PAD];   // [j][k]
    __shared__ float sb[HID];
    __shared__ __align__(16) float sWg[HID * HID];      // [j][c]
    for (int i = threadIdx.x; i < F_IN * HID; i += blockDim.x) {
        int k = i / HID, j = i % HID;
        sWeT[j * F_PAD + k] = Wemb[i];
    }
    for (int i = threadIdx.x; i < HID; i += blockDim.x) {
        sWeT[i * F_PAD + 22] = 0.0f;
        sWeT[i * F_PAD + 23] = 0.0f;
    }
    for (int i = threadIdx.x; i < HID * HID; i += blockDim.x) sWg[i] = Wgcn[i];
    if (threadIdx.x < HID) sb[threadIdx.x] = bemb[threadIdx.x];
    __syncthreads();

    int node = blockIdx.x * blockDim.x + threadIdx.x;
    if (node >= n) return;

    float xr[F_PAD];
    const float* xp = x + (size_t)node * F_IN;
#pragma unroll
    for (int k = 0; k < F_IN; k++) xr[k] = xp[k];
    xr[22] = 0.0f; xr[23] = 0.0f;

    float acc[HID];
#pragma unroll
    for (int c = 0; c < HID; c++) acc[c] = 0.0f;

    for (int j = 0; j < HID; j++) {
        const float4* wr = (const float4*)(sWeT + j * F_PAD);
        float t = sb[j];
#pragma unroll
        for (int q = 0; q < F_PAD / 4; q++) {
            float4 w = wr[q];
            t = fmaf(xr[4*q+0], w.x, t);
            t = fmaf(xr[4*q+1], w.y, t);
            t = fmaf(xr[4*q+2], w.z, t);
            t = fmaf(xr[4*q+3], w.w, t);
        }
        t = fmaxf(t, 0.0f);
        const float4* gr = (const float4*)(sWg + j * HID);
#pragma unroll
        for (int q = 0; q < HID / 4; q++) {
            float4 g = gr[q];
            acc[4*q+0] = fmaf(t, g.x, acc[4*q+0]);
            acc[4*q+1] = fmaf(t, g.y, acc[4*q+1]);
            acc[4*q+2] = fmaf(t, g.z, acc[4*q+2]);
            acc[4*q+3] = fmaf(t, g.w, acc[4*q+3]);
        }
    }

    float dis = rsqrtf((float)g_cnt[node] + 1.0f);

    float4* hp = (float4*)(g_hs + (size_t)node * HID);
#pragma unroll
    for (int c = 0; c < HID / 4; c++)
        hp[c] = make_float4(acc[4*c] * dis, acc[4*c+1] * dis,
                            acc[4*c+2] * dis, acc[4*c+3] * dis);
}

// ---------------- gather + fused BN partials ----------------
// One warp per node; lane = feature column. Adjacency row loaded coalesced,
// sources shfl-broadcast, hs rows gathered from L2. Block-level BN reduction
// (32 nodes/block) ends in one RED per column per block.
__global__ void __launch_bounds__(1024)
k_gather(const float* __restrict__ bgcn, int n) {
    int wid = threadIdx.x >> 5;
    int lane = threadIdx.x & 31;
    int node = blockIdx.x * 32 + wid;

    float val = 0.0f;
    if (node < n) {
        int cnt = g_cnt[node];
        float dis = rsqrtf((float)cnt + 1.0f);
        int m = min(cnt, MAXDEG);

        const int* row = g_pad + (size_t)node * MAXDEG;
        int s0 = (lane < m) ? row[lane] : 0;
        int s1 = (32 + lane < m) ? row[32 + lane] : 0;

        float a0 = g_hs[(size_t)node * HID + lane];
        float a1 = 0.0f, a2 = 0.0f, a3 = 0.0f;

        int m0 = min(m, 32);
        int j = 0;
        for (; j + 4 <= m0; j += 4) {
            int sa = __shfl_sync(0xffffffffu, s0, j);
            int sb = __shfl_sync(0xffffffffu, s0, j + 1);
            int sc = __shfl_sync(0xffffffffu, s0, j + 2);
            int sd = __shfl_sync(0xffffffffu, s0, j + 3);
            float va = g_hs[(size_t)sa * HID + lane];
            float vb = g_hs[(size_t)sb * HID + lane];
            float vc = g_hs[(size_t)sc * HID + lane];
            float vd = g_hs[(size_t)sd * HID + lane];
            a0 += va; a1 += vb; a2 += vc; a3 += vd;
        }
        for (; j < m0; j++) {
            int sa = __shfl_sync(0xffffffffu, s0, j);
            a0 += g_hs[(size_t)sa * HID + lane];
        }
        for (j = 32; j < m; j++) {
            int sa = __shfl_sync(0xffffffffu, s1, j - 32);
            a1 += g_hs[(size_t)sa * HID + lane];
        }

        float acc = (a0 + a1) + (a2 + a3);
        val = fmaf(dis, acc, bgcn[lane]);
        g_agg[(size_t)node * HID + lane] = val;
    }

    // block BN reduction: sh[w][c] then 2 warps tree-sum columns
    __shared__ float sh_s[32][33];
    __shared__ float sh_q[32][33];
    sh_s[wid][lane] = val;
    sh_q[wid][lane] = val * val;
    __syncthreads();
    if (threadIdx.x < 32) {
        int c = threadIdx.x;
        float t = 0.0f;
#pragma unroll
        for (int w = 0; w < 32; w++) t += sh_s[w][c];
        atomicAdd(&g_sum[c], t);
    } else if (threadIdx.x < 64) {
        int c = threadIdx.x - 32;
        float t = 0.0f;
#pragma unroll
        for (int w = 0; w < 32; w++) t += sh_q[w][c];
        atomicAdd(&g_sumsq[c], t);
    }
}

// ---------------- BN finalize: scale/shift ----------------
__global__ void k_bnfin(const float* __restrict__ gamma, const float* __restrict__ beta, int n) {
    int c = threadIdx.x;
    if (c < HID) {
        float inv_n = 1.0f / (float)n;
        float mean = g_sum[c] * inv_n;
        float var = g_sumsq[c] * inv_n - mean * mean;
        float sc = gamma[c] * rsqrtf(var + BN_EPS);
        g_scale[c] = sc;
        g_shift[c] = beta[c] - mean * sc;
    }
}

// ---------------- classifier: out = relu(BN(agg)) @ W_cls + b_cls ----------------
__global__ void __launch_bounds__(128)
k_cls(const float* __restrict__ Wcls, const float* __restrict__ bcls,
      float* __restrict__ out, int n) {
    __shared__ float sW[HID * N_CLS];
    __shared__ float sbc[N_CLS];
    __shared__ float ssc[HID];
    __shared__ float ssh[HID];
    for (int i = threadIdx.x; i < HID * N_CLS; i += blockDim.x) sW[i] = Wcls[i];
    if (threadIdx.x < N_CLS) sbc[threadIdx.x] = bcls[threadIdx.x];
    if (threadIdx.x < HID) {
        ssc[threadIdx.x] = g_scale[threadIdx.x];
        ssh[threadIdx.x] = g_shift[threadIdx.x];
    }
    __syncthreads();

    int node = blockIdx.x * blockDim.x + threadIdx.x;
    if (node >= n) return;

    float acc[N_CLS];
#pragma unroll
    for (int c = 0; c < N_CLS; c++) acc[c] = sbc[c];

    const float4* ap = (const float4*)(g_agg + (size_t)node * HID);
#pragma unroll
    for (int q = 0; q < HID / 4; q++) {
        float4 v4 = ap[q];
        float vv[4] = {v4.x, v4.y, v4.z, v4.w};
#pragma unroll
        for (int u = 0; u < 4; u++) {
            int j = q * 4 + u;
            float v = fmaxf(fmaf(vv[u], ssc[j], ssh[j]), 0.0f);
#pragma unroll
            for (int c = 0; c < N_CLS; c++) acc[c] = fmaf(v, sW[j * N_CLS + c], acc[c]);
        }
    }
    float* op = out + (size_t)node * N_CLS;
#pragma unroll
    for (int c = 0; c < N_CLS; c++) op[c] = acc[c];
}

// ---------------- launch ----------------
extern "C" void kernel_launch(void* const* d_in, const int* in_sizes, int n_in,
                              void* d_out, int out_size) {
    const float* x     = (const float*)d_in[0];
    const void*  ei    = d_in[1];
    const float* Wemb  = (const float*)d_in[2];
    const float* bemb  = (const float*)d_in[3];
    const float* Wgcn  = (const float*)d_in[4];
    const float* bgcn  = (const float*)d_in[5];
    const float* gamma = (const float*)d_in[6];
    const float* beta  = (const float*)d_in[7];
    const float* Wcls  = (const float*)d_in[8];
    const float* bcls  = (const float*)d_in[9];
    float* out = (float*)d_out;

    int n = in_sizes[0] / F_IN;      // 150000
    int e = in_sizes[1] / 2;         // 2400000

    k_detect<<<1, 32>>>((const long long*)ei, n);
    k_zero<<<(n + 255) / 256, 256>>>(n);
    k_build<<<(e + 255) / 256, 256>>>(ei, e);
    k_mlp<<<(n + 127) / 128, 128>>>(x, Wemb, bemb, Wgcn, n);
    k_gather<<<(n + 31) / 32, 1024>>>(bgcn, n);
    k_bnfin<<<1, 32>>>(gamma, beta, n);
    k_cls<<<(n + 127) / 128, 128>>>(Wcls, bcls, out, n);
}

// round 5
// speedup vs baseline: 1.0201x; 1.0201x over previous
#include <cuda_runtime.h>
#include <stdint.h>

#define N_MAXN 150000
#define E_MAXE 2400000
#define F_IN 22
#define F_PAD 24
#define X_PAD 23
#define HID 32
#define N_CLS 6
#define BN_EPS 1e-5f
#define MAXDEG 64

// ---------------- device scratch (no allocations allowed) ----------------
__device__ __align__(16) float g_hs[N_MAXN * HID];     // dis[node] * ((relu(xWe+be))Wg)
__device__ __align__(16) float g_agg[N_MAXN * HID];    // aggregated messages
__device__ int   g_cnt[N_MAXN];                        // in-degree (excl. self loop)
__device__ int   g_pad[(size_t)N_MAXN * MAXDEG];       // padded CSR: src lists per dst
__device__ float g_sum[HID];
__device__ float g_sumsq[HID];
__device__ float g_scale[HID];
__device__ float g_shift[HID];
__device__ int   g_is64;

// ---------------- dtype detection for edge_index (1 warp) ----------------
__global__ void k_detect(const long long* __restrict__ ei, int n) {
    int t = threadIdx.x;
    long long v0 = ei[t];
    long long v1 = ei[t + 32];
    int bad = (v0 < 0) | (v0 >= (long long)n) | (v1 < 0) | (v1 >= (long long)n);
    unsigned m = __ballot_sync(0xffffffffu, bad);
    if (t == 0) g_is64 = (m == 0u);
}

// ---------------- zero counters + BN accumulators ----------------
__global__ void k_zero(int n) {
    int i = blockIdx.x * blockDim.x + threadIdx.x;
    if (i < n) g_cnt[i] = 0;
    if (i < HID) { g_sum[i] = 0.0f; g_sumsq[i] = 0.0f; }
}

// ---------------- build padded CSR: pad[d][pos] = s ----------------
__global__ void k_build(const void* __restrict__ ei, int e) {
    int i = blockIdx.x * blockDim.x + threadIdx.x;
    if (i >= e) return;
    int s, d;
    if (g_is64) {
        const long long* p = (const long long*)ei;
        s = (int)p[i];
        d = (int)p[(size_t)e + i];
    } else {
        const int* p = (const int*)ei;
        s = p[i];
        d = p[(size_t)e + i];
    }
    int pos = atomicAdd(&g_cnt[d], 1);
    if (pos < MAXDEG) g_pad[(size_t)d * MAXDEG + pos] = s;
}

// ---------------- fused MLP: hs = dis * (relu(x@W_emb + b_emb) @ W_gcn) ----------------
// x staged per block via coalesced loads (row pad 23 -> conflict-free LDS).
// j-loop unrolled 4x for independent LDS/FMA chains.
__global__ void __launch_bounds__(128)
k_mlp(const float* __restrict__ x, const float* __restrict__ Wemb,
      const float* __restrict__ bemb, const float* __restrict__ Wgcn, int n) {
    __shared__ __align__(16) float sWeT[HID * F_PAD];   // [j][k]
    __shared__ float sb[HID];
    __shared__ __align__(16) float sWg[HID * HID];      // [j][c]
    __shared__ float sx[128 * X_PAD];

    for (int i = threadIdx.x; i < F_IN * HID; i += blockDim.x) {
        int k = i / HID, j = i % HID;
        sWeT[j * F_PAD + k] = Wemb[i];
    }
    for (int i = threadIdx.x; i < HID; i += blockDim.x) {
        sWeT[i * F_PAD + 22] = 0.0f;
        sWeT[i * F_PAD + 23] = 0.0f;
    }
    for (int i = threadIdx.x; i < HID * HID; i += blockDim.x) sWg[i] = Wgcn[i];
    if (threadIdx.x < HID) sb[threadIdx.x] = bemb[threadIdx.x];

    // coalesced stage of this block's x rows
    int base = blockIdx.x * 128;
    int cnt_nodes = min(128, n - base);
    if (cnt_nodes > 0) {
        int total = cnt_nodes * F_IN;
        const float* xs = x + (size_t)base * F_IN;
        for (int i = threadIdx.x; i < total; i += blockDim.x) {
            int r = i / F_IN, k = i - r * F_IN;
            sx[r * X_PAD + k] = xs[i];
        }
    }
    __syncthreads();

    int node = base + threadIdx.x;
    if (node >= n) return;

    float xr[F_PAD];
#pragma unroll
    for (int k = 0; k < F_IN; k++) xr[k] = sx[threadIdx.x * X_PAD + k];
    xr[22] = 0.0f; xr[23] = 0.0f;

    float acc[HID];
#pragma unroll
    for (int c = 0; c < HID; c++) acc[c] = 0.0f;

#pragma unroll 4
    for (int j = 0; j < HID; j++) {
        const float4* wr = (const float4*)(sWeT + j * F_PAD);
        float t = sb[j];
#pragma unroll
        for (int q = 0; q < F_PAD / 4; q++) {
            float4 w = wr[q];
            t = fmaf(xr[4*q+0], w.x, t);
            t = fmaf(xr[4*q+1], w.y, t);
            t = fmaf(xr[4*q+2], w.z, t);
            t = fmaf(xr[4*q+3], w.w, t);
        }
        t = fmaxf(t, 0.0f);
        const float4* gr = (const float4*)(sWg + j * HID);
#pragma unroll
        for (int q = 0; q < HID / 4; q++) {
            float4 g = gr[q];
            acc[4*q+0] = fmaf(t, g.x, acc[4*q+0]);
            acc[4*q+1] = fmaf(t, g.y, acc[4*q+1]);
            acc[4*q+2] = fmaf(t, g.z, acc[4*q+2]);
            acc[4*q+3] = fmaf(t, g.w, acc[4*q+3]);
        }
    }

    float dis = rsqrtf((float)g_cnt[node] + 1.0f);

    float4* hp = (float4*)(g_hs + (size_t)node * HID);
#pragma unroll
    for (int c = 0; c < HID / 4; c++)
        hp[c] = make_float4(acc[4*c] * dis, acc[4*c+1] * dis,
                            acc[4*c+2] * dis, acc[4*c+3] * dis);
}

// ---------------- gather: agg[d] = dis[d]*(sum hs[s] + hs[d]) + b_gcn (R3 version) ----------------
__global__ void __launch_bounds__(256)
k_gather(const float* __restrict__ bgcn, int n) {
    int warp = (blockIdx.x * 256 + threadIdx.x) >> 5;
    int lane = threadIdx.x & 31;
    if (warp >= n) return;
    int node = warp;

    int cnt = g_cnt[node];
    float dis = rsqrtf((float)cnt + 1.0f);
    int m = min(cnt, MAXDEG);

    const int* row = g_pad + (size_t)node * MAXDEG;
    int s0 = (lane < m) ? row[lane] : 0;
    int s1 = (32 + lane < m) ? row[32 + lane] : 0;

    float a0 = g_hs[(size_t)node * HID + lane];
    float a1 = 0.0f, a2 = 0.0f, a3 = 0.0f;

    int m0 = min(m, 32);
    int j = 0;
    for (; j + 4 <= m0; j += 4) {
        int sa = __shfl_sync(0xffffffffu, s0, j);
        int sb = __shfl_sync(0xffffffffu, s0, j + 1);
        int sc = __shfl_sync(0xffffffffu, s0, j + 2);
        int sd = __shfl_sync(0xffffffffu, s0, j + 3);
        float va = g_hs[(size_t)sa * HID + lane];
        float vb = g_hs[(size_t)sb * HID + lane];
        float vc = g_hs[(size_t)sc * HID + lane];
        float vd = g_hs[(size_t)sd * HID + lane];
        a0 += va; a1 += vb; a2 += vc; a3 += vd;
    }
    for (; j < m0; j++) {
        int sa = __shfl_sync(0xffffffffu, s0, j);
        a0 += g_hs[(size_t)sa * HID + lane];
    }
    for (j = 32; j < m; j++) {
        int sa = __shfl_sync(0xffffffffu, s1, j - 32);
        a1 += g_hs[(size_t)sa * HID + lane];
    }

    float acc = (a0 + a1) + (a2 + a3);
    g_agg[(size_t)node * HID + lane] = fmaf(dis, acc, bgcn[lane]);
}

// ---------------- BN statistics: per-column sum / sumsq (R3 version) ----------------
__global__ void __launch_bounds__(256)
k_bnsum(int n) {
    int col = threadIdx.x & 31;
    float s = 0.0f, s2 = 0.0f;
    int total = n * HID;
    int stride = gridDim.x * blockDim.x;
    for (int idx = blockIdx.x * blockDim.x + threadIdx.x; idx < total; idx += stride) {
        float v = g_agg[idx];
        s += v;
        s2 = fmaf(v, v, s2);
    }
    __shared__ float sh[2][8][32];
    int w = threadIdx.x >> 5;
    sh[0][w][col] = s;
    sh[1][w][col] = s2;
    __syncthreads();
    if (threadIdx.x < 32) {
        float ts = 0.0f, t2 = 0.0f;
#pragma unroll
        for (int i = 0; i < 8; i++) { ts += sh[0][i][col]; t2 += sh[1][i][col]; }
        atomicAdd(&g_sum[col], ts);
        atomicAdd(&g_sumsq[col], t2);
    }
}

// ---------------- BN finalize: scale/shift ----------------
__global__ void k_bnfin(const float* __restrict__ gamma, const float* __restrict__ beta, int n) {
    int c = threadIdx.x;
    if (c < HID) {
        float inv_n = 1.0f / (float)n;
        float mean = g_sum[c] * inv_n;
        float var = g_sumsq[c] * inv_n - mean * mean;
        float sc = gamma[c] * rsqrtf(var + BN_EPS);
        g_scale[c] = sc;
        g_shift[c] = beta[c] - mean * sc;
    }
}

// ---------------- classifier: out = relu(BN(agg)) @ W_cls + b_cls ----------------
__global__ void __launch_bounds__(128)
k_cls(const float* __restrict__ Wcls, const float* __restrict__ bcls,
      float* __restrict__ out, int n) {
    __shared__ float sW[HID * N_CLS];
    __shared__ float sbc[N_CLS];
    __shared__ float ssc[HID];
    __shared__ float ssh[HID];
    for (int i = threadIdx.x; i < HID * N_CLS; i += blockDim.x) sW[i] = Wcls[i];
    if (threadIdx.x < N_CLS) sbc[threadIdx.x] = bcls[threadIdx.x];
    if (threadIdx.x < HID) {
        ssc[threadIdx.x] = g_scale[threadIdx.x];
        ssh[threadIdx.x] = g_shift[threadIdx.x];
    }
    __syncthreads();

    int node = blockIdx.x * blockDim.x + threadIdx.x;
    if (node >= n) return;

    float acc[N_CLS];
#pragma unroll
    for (int c = 0; c < N_CLS; c++) acc[c] = sbc[c];

    const float4* ap = (const float4*)(g_agg + (size_t)node * HID);
#pragma unroll
    for (int q = 0; q < HID / 4; q++) {
        float4 v4 = ap[q];
        float vv[4] = {v4.x, v4.y, v4.z, v4.w};
#pragma unroll
        for (int u = 0; u < 4; u++) {
            int j = q * 4 + u;
            float v = fmaxf(fmaf(vv[u], ssc[j], ssh[j]), 0.0f);
#pragma unroll
            for (int c = 0; c < N_CLS; c++) acc[c] = fmaf(v, sW[j * N_CLS + c], acc[c]);
        }
    }
    float* op = out + (size_t)node * N_CLS;
#pragma unroll
    for (int c = 0; c < N_CLS; c++) op[c] = acc[c];
}

// ---------------- launch ----------------
extern "C" void kernel_launch(void* const* d_in, const int* in_sizes, int n_in,
                              void* d_out, int out_size) {
    const float* x     = (const float*)d_in[0];
    const void*  ei    = d_in[1];
    const float* Wemb  = (const float*)d_in[2];
    const float* bemb  = (const float*)d_in[3];
    const float* Wgcn  = (const float*)d_in[4];
    const float* bgcn  = (const float*)d_in[5];
    const float* gamma = (const float*)d_in[6];
    const float* beta  = (const float*)d_in[7];
    const float* Wcls  = (const float*)d_in[8];
    const float* bcls  = (const float*)d_in[9];
    float* out = (float*)d_out;

    int n = in_sizes[0] / F_IN;      // 150000
    int e = in_sizes[1] / 2;         // 2400000

    k_detect<<<1, 32>>>((const long long*)ei, n);
    k_zero<<<(n + 255) / 256, 256>>>(n);
    k_build<<<(e + 255) / 256, 256>>>(ei, e);
    k_mlp<<<(n + 127) / 128, 128>>>(x, Wemb, bemb, Wgcn, n);
    k_gather<<<(n * 32 + 255) / 256, 256>>>(bgcn, n);
    k_bnsum<<<2048, 256>>>(n);
    k_bnfin<<<1, 32>>>(gamma, beta, n);
    k_cls<<<(n + 127) / 128, 128>>>(Wcls, bcls, out, n);
}